// round 15
// baseline (speedup 1.0000x reference)
#include <cuda_runtime.h>
#include <cuda_fp16.h>
#include <math.h>
#include <stdint.h>

#define NN 50000
#define EE 800000
#define ET 850000   // EE + NN self loops
#define NB 196      // ceil(NN/256)
#define GX128 391   // ceil(NN/128)
#define GPAD 136    // padded row: 136 fp16 = 272B (conflict-free ldmatrix)
#define SMEM_MMA_SZ (128 * GPAD * 2)   // 34816 B: single fp16 B image

// ---------------- scratch (static device allocations only) ----------------
__device__ __align__(16) __half g_x_h [(size_t)NN * 128];
__device__ __align__(16) __half g_xl_h[(size_t)NN * 128];
__device__ __align__(16) __half g_xr_h[(size_t)NN * 128];
__device__ __align__(16) __half g_h1h[(size_t)NN * 128];
__device__ __align__(16) __half g_h2h[(size_t)NN * 128];
__device__ float g_hlr[(size_t)NN * 32];
__device__ int   g_deg[NN];
__device__ int   g_rowptr[NN + 1];
__device__ int   g_cursor[NN];
__device__ int   g_csr[ET];
__device__ int   g_part[256];
__device__ int   g_is64;
__device__ __align__(16) __half g_wimg[5][128 * GPAD];

__device__ __forceinline__ float lrelu(float x) { return x > 0.f ? x : 0.2f * x; }
__device__ __forceinline__ float elu1 (float x) { return x > 0.f ? x : expm1f(x); }

__device__ __forceinline__ uint32_t smem_u32(const void* p) {
    uint32_t a;
    asm("{ .reg .u64 t; cvta.to.shared.u64 t, %1; cvt.u32.u64 %0, t; }"
        : "=r"(a) : "l"(p));
    return a;
}
__device__ __forceinline__ uint32_t pkh(float2 f) {
    __half2 h = __float22half2_rn(f);
    return *(uint32_t*)&h;
}

__device__ __forceinline__ void ldsm_x4t(uint32_t& r0, uint32_t& r1,
                                         uint32_t& r2, uint32_t& r3, uint32_t addr) {
    asm volatile("ldmatrix.sync.aligned.m8n8.x4.trans.shared.b16 {%0,%1,%2,%3}, [%4];"
        : "=r"(r0), "=r"(r1), "=r"(r2), "=r"(r3) : "r"(addr));
}
__device__ __forceinline__ void mma16816(float* d, const uint32_t* a,
                                         uint32_t b0, uint32_t b1) {
    asm volatile(
        "mma.sync.aligned.m16n8k16.row.col.f32.f16.f16.f32 "
        "{%0,%1,%2,%3}, {%4,%5,%6,%7}, {%8,%9}, {%0,%1,%2,%3};"
        : "+f"(d[0]), "+f"(d[1]), "+f"(d[2]), "+f"(d[3])
        : "r"(a[0]), "r"(a[1]), "r"(a[2]), "r"(a[3]), "r"(b0), "r"(b1));
}

// ---------------- weight convert kernel: W[k][n] -> fp16 image --------------
__global__ void wconv(const float* __restrict__ w0, const float* __restrict__ w1,
                      const float* __restrict__ w2, const float* __restrict__ w3,
                      const float* __restrict__ w4) {
    int b = blockIdx.y;
    const float* W = (b == 0) ? w0 : (b == 1) ? w1 : (b == 2) ? w2 : (b == 3) ? w3 : w4;
    int k = blockIdx.x, n = threadIdx.x;
    g_wimg[b][k * GPAD + n] = __float2half_rn(W[(size_t)k * 128 + n]);
}

// ---------------- x fp32 -> fp16 (identical rounding to in-GEMM path) -------
__global__ void xconv(const float* __restrict__ x) {
    size_t i = ((size_t)blockIdx.x * blockDim.x + threadIdx.x) * 8;
    if (i >= (size_t)NN * 128) return;
    float4 a = *(const float4*)&x[i];
    float4 b = *(const float4*)&x[i + 4];
    uint4 o;
    o.x = pkh(make_float2(a.x, a.y));
    o.y = pkh(make_float2(a.z, a.w));
    o.z = pkh(make_float2(b.x, b.y));
    o.w = pkh(make_float2(b.z, b.w));
    *(uint4*)&g_x_h[i] = o;
}

// ---------------- tensor-core GEMM: C[NN,128] = A[NN,128] @ W ---------------
// fp16 in/out, fp32 accum. Warp tile 32(M)x128(N); 128-thread CTA = 128 rows.
// Two sequential 64-col halves (acc = 64 regs). grid=(391, nmat).
__global__ void __launch_bounds__(128) mma_gemm(
    const __half* __restrict__ A, int i0, int i1,
    __half* __restrict__ C0, __half* __restrict__ C1,
    const float* __restrict__ bias, int act) {
    extern __shared__ __align__(16) __half sB[];   // fp16 image [128*GPAD]
    const int t = threadIdx.x, lane = t & 31, wid = t >> 5;
    const int mat = blockIdx.y;
    const int img = mat ? i1 : i0;
    __half* C = mat ? C1 : C0;
    const int m0 = blockIdx.x * 128 + wid * 32;

    // stage B image: 34816 B = 2176 uint4
    {
        const uint4* src = (const uint4*)&g_wimg[img][0];
        uint4* dst = (uint4*)sB;
        for (int i = t; i < 2176; i += 128) dst[i] = src[i];
    }
    __syncthreads();

    const int g  = lane >> 2;
    const int cp = (lane & 3) * 2;
    const int r0 = m0 + g, r1 = m0 + g + 8, r2 = m0 + g + 16, r3 = m0 + g + 24;
    const bool v0 = r0 < NN, v1 = r1 < NN, v2 = r2 < NN, v3 = r3 < NN;

    const int bi   = lane >> 3;
    const int brow = (lane & 7) + (bi & 1) * 8;
    const int bcol = (bi >> 1) * 8;
    const uint32_t sbH = smem_u32(sB);

#pragma unroll
    for (int nh = 0; nh < 2; nh++) {
        const uint32_t hoff = (uint32_t)nh * 128;
        float acc0[8][4];   // rows r0/r1
        float acc1[8][4];   // rows r2/r3
#pragma unroll
        for (int i = 0; i < 8; i++)
#pragma unroll
            for (int j = 0; j < 4; j++) { acc0[i][j] = 0.f; acc1[i][j] = 0.f; }

        for (int ks = 0; ks < 8; ks++) {
            const int k0 = ks * 16;
            uint32_t ah0[4], ah1[4];
            ah0[0] = v0 ? *(const uint32_t*)&A[(size_t)r0 * 128 + k0 + cp]     : 0u;
            ah0[1] = v1 ? *(const uint32_t*)&A[(size_t)r1 * 128 + k0 + cp]     : 0u;
            ah0[2] = v0 ? *(const uint32_t*)&A[(size_t)r0 * 128 + k0 + cp + 8] : 0u;
            ah0[3] = v1 ? *(const uint32_t*)&A[(size_t)r1 * 128 + k0 + cp + 8] : 0u;
            ah1[0] = v2 ? *(const uint32_t*)&A[(size_t)r2 * 128 + k0 + cp]     : 0u;
            ah1[1] = v3 ? *(const uint32_t*)&A[(size_t)r3 * 128 + k0 + cp]     : 0u;
            ah1[2] = v2 ? *(const uint32_t*)&A[(size_t)r2 * 128 + k0 + cp + 8] : 0u;
            ah1[3] = v3 ? *(const uint32_t*)&A[(size_t)r3 * 128 + k0 + cp + 8] : 0u;

            const uint32_t rowoff = (uint32_t)((k0 + brow) * GPAD + bcol) * 2 + hoff;
#pragma unroll
            for (int ng = 0; ng < 4; ng++) {
                uint32_t b0, b1, b2, b3;
                ldsm_x4t(b0, b1, b2, b3, sbH + rowoff + ng * 32);
                mma16816(acc0[2 * ng],     ah0, b0, b1);
                mma16816(acc0[2 * ng + 1], ah0, b2, b3);
                mma16816(acc1[2 * ng],     ah1, b0, b1);
                mma16816(acc1[2 * ng + 1], ah1, b2, b3);
            }
        }

        // epilogue for this 64-col half
#pragma unroll
        for (int nt = 0; nt < 8; nt++) {
            int gc = nh * 64 + nt * 8 + cp;
            float b0v = 0.f, b1v = 0.f;
            if (bias) { b0v = bias[gc]; b1v = bias[gc + 1]; }
            float e00 = acc0[nt][0] + b0v, e01 = acc0[nt][1] + b1v;
            float e10 = acc0[nt][2] + b0v, e11 = acc0[nt][3] + b1v;
            float e20 = acc1[nt][0] + b0v, e21 = acc1[nt][1] + b1v;
            float e30 = acc1[nt][2] + b0v, e31 = acc1[nt][3] + b1v;
            if (act == 1) {
                e00 = elu1(e00); e01 = elu1(e01); e10 = elu1(e10); e11 = elu1(e11);
                e20 = elu1(e20); e21 = elu1(e21); e30 = elu1(e30); e31 = elu1(e31);
            }
            if (v0) *(uint32_t*)&C[(size_t)r0 * 128 + gc] = pkh(make_float2(e00, e01));
            if (v1) *(uint32_t*)&C[(size_t)r1 * 128 + gc] = pkh(make_float2(e10, e11));
            if (v2) *(uint32_t*)&C[(size_t)r2 * 128 + gc] = pkh(make_float2(e20, e21));
            if (v3) *(uint32_t*)&C[(size_t)r3 * 128 + gc] = pkh(make_float2(e30, e31));
        }
    }
}

// ---------------- init deg=0 + dtype detect (block 0) ----------------------
__global__ void init_detect(const void* ei) {
    int i = blockIdx.x * blockDim.x + threadIdx.x;
    if (i < NN) g_deg[i] = 0;
    if (blockIdx.x == 0) {
        __shared__ int cnt;
        if (threadIdx.x == 0) cnt = 0;
        __syncthreads();
        const unsigned* p = (const unsigned*)ei;
        int nz = 0;
        for (int k = threadIdx.x; k < 2048; k += 256)
            if (p[2 * k + 1] != 0u) nz++;
        if (nz) atomicAdd(&cnt, nz);
        __syncthreads();
        if (threadIdx.x == 0) g_is64 = (cnt < 8) ? 1 : 0;
    }
}

__device__ __forceinline__ int edge_val(const void* ei, int idx, int is64) {
    if (is64) return (int)((const long long*)ei)[idx];
    return ((const int*)ei)[idx];
}

__global__ void degree_k(const void* ei) {
    int i = blockIdx.x * blockDim.x + threadIdx.x;
    if (i >= EE) return;
    int is64 = g_is64;
    int dst = edge_val(ei, EE + i, is64);
    atomicAdd(&g_deg[dst], 1);
}

// ---------------- parallel scan over (deg[i]+1) ----------------------------
__global__ void scan_part() {
    int t = threadIdx.x, lane = t & 31, w = t >> 5;
    int i = blockIdx.x * 256 + t;
    int v = (i < NN) ? g_deg[i] + 1 : 0;
#pragma unroll
    for (int off = 16; off >= 1; off >>= 1) v += __shfl_xor_sync(0xffffffffu, v, off);
    __shared__ int ws[8];
    if (lane == 0) ws[w] = v;
    __syncthreads();
    if (t == 0) {
        int s = 0;
#pragma unroll
        for (int k = 0; k < 8; k++) s += ws[k];
        g_part[blockIdx.x] = s;
    }
}

__global__ void scan_mid() {
    int t = threadIdx.x, lane = t & 31, w = t >> 5;
    int d = (t < NB) ? g_part[t] : 0;
    int v = d;
#pragma unroll
    for (int off = 1; off < 32; off <<= 1) {
        int u = __shfl_up_sync(0xffffffffu, v, off);
        if (lane >= off) v += u;
    }
    __shared__ int ws[8];
    if (lane == 31) ws[w] = v;
    __syncthreads();
    if (w == 0 && lane < 8) {
        int s = ws[lane];
#pragma unroll
        for (int off = 1; off < 8; off <<= 1) {
            int u = __shfl_up_sync(0xffu, s, off);
            if (lane >= off) s += u;
        }
        ws[lane] = s;
    }
    __syncthreads();
    int incl = v + (w > 0 ? ws[w - 1] : 0);
    if (t < NB) g_part[t] = incl - d;
    if (t == 255) g_rowptr[NN] = incl;
}

__global__ void scan_add() {
    int t = threadIdx.x, lane = t & 31, w = t >> 5;
    int i = blockIdx.x * 256 + t;
    int d = (i < NN) ? g_deg[i] + 1 : 0;
    int v = d;
#pragma unroll
    for (int off = 1; off < 32; off <<= 1) {
        int u = __shfl_up_sync(0xffffffffu, v, off);
        if (lane >= off) v += u;
    }
    __shared__ int ws[8];
    if (lane == 31) ws[w] = v;
    __syncthreads();
    if (w == 0 && lane < 8) {
        int s = ws[lane];
#pragma unroll
        for (int off = 1; off < 8; off <<= 1) {
            int u = __shfl_up_sync(0xffu, s, off);
            if (lane >= off) s += u;
        }
        ws[lane] = s;
    }
    __syncthreads();
    int excl = g_part[blockIdx.x] + v - d + (w > 0 ? ws[w - 1] : 0);
    if (i < NN) {
        g_rowptr[i] = excl;
        g_csr[excl] = i;
        g_cursor[i] = excl + 1;
    }
}

__global__ void scatter_k(const void* ei) {
    int i = blockIdx.x * blockDim.x + threadIdx.x;
    if (i >= EE) return;
    int is64 = g_is64;
    int s = edge_val(ei, i, is64);
    int d = edge_val(ei, EE + i, is64);
    int pos = atomicAdd(&g_cursor[d], 1);
    g_csr[pos] = s;
}

// ---------------- conv1 aggregation: warp per node, 8-head online softmax --
__global__ void conv1_agg(const float* __restrict__ att1, const float* __restrict__ b1) {
    int gw   = (blockIdx.x * blockDim.x + threadIdx.x) >> 5;
    int lane = threadIdx.x & 31;
    int d = gw;
    const int c4 = lane * 4;

    uint2 xru = *(const uint2*)&g_xr_h[(size_t)d * 128 + c4];
    float2 xr01 = __half22float2(*(__half2*)&xru.x);
    float2 xr23 = __half22float2(*(__half2*)&xru.y);
    const float4 av = *(const float4*)&att1[c4];
    const float4 bb = *(const float4*)&b1[c4];
    const int beg = g_rowptr[d], end = g_rowptr[d + 1];
    const int last = end - 1;

    float m = -INFINITY, s = 0.f;
    float ax = 0.f, ay = 0.f, az = 0.f, aw = 0.f;

    int i4[4];
    uint2 r[4];
#pragma unroll
    for (int k = 0; k < 4; k++) {
        int j0 = min(beg + k, last);
        int j4 = min(beg + 4 + k, last);
        int src = g_csr[j0];
        i4[k] = g_csr[j4];
        r[k] = *(const uint2*)&g_xl_h[(size_t)src * 128 + c4];
    }

    for (int j = beg; j < end; j++) {
        int inew = g_csr[min(j + 8, last)];
        uint2 rnew = *(const uint2*)&g_xl_h[(size_t)i4[0] * 128 + c4];

        float2 x01 = __half22float2(*(__half2*)&r[0].x);
        float2 x23 = __half22float2(*(__half2*)&r[0].y);
        float ex = lrelu(x01.x + xr01.x);
        float ey = lrelu(x01.y + xr01.y);
        float ez = lrelu(x23.x + xr23.x);
        float ew = lrelu(x23.y + xr23.y);
        float p = ex * av.x + ey * av.y + ez * av.z + ew * av.w;
        p += __shfl_xor_sync(0xffffffffu, p, 1);
        p += __shfl_xor_sync(0xffffffffu, p, 2);
        float mn = fmaxf(m, p);
        float f  = __expf(m - mn);
        float wt = __expf(p - mn);
        s  = s * f + wt;
        ax = ax * f + x01.x * wt;
        ay = ay * f + x01.y * wt;
        az = az * f + x23.x * wt;
        aw = aw * f + x23.y * wt;
        m = mn;

        r[0] = r[1]; r[1] = r[2]; r[2] = r[3]; r[3] = rnew;
        i4[0] = i4[1]; i4[1] = i4[2]; i4[2] = i4[3]; i4[3] = inew;
    }
    float inv = 1.f / s;
    float o0 = elu1(ax * inv + bb.x);
    float o1 = elu1(ay * inv + bb.y);
    float o2 = elu1(az * inv + bb.z);
    float o3 = elu1(aw * inv + bb.w);
    uint2 ov;
    ov.x = pkh(make_float2(o0, o1));
    ov.y = pkh(make_float2(o2, o3));
    *(uint2*)&g_h1h[(size_t)d * 128 + c4] = ov;
}

// ---------------- conv2 transforms (fp16 h input) ---------------------------
__global__ void conv2_transform(const __half* __restrict__ h,
                                const float* __restrict__ Wl2,
                                const float* __restrict__ Wr2) {
    __shared__ float sw[128 * 32];
    __shared__ float sh[8][128];
    int t = threadIdx.x;
    for (int i = t; i < 128 * 16; i += 256) {
        int k = i >> 4, c = i & 15;
        sw[k * 32 + c]      = Wl2[i];
        sw[k * 32 + 16 + c] = Wr2[i];
    }
    int row0 = blockIdx.x * 8;
    for (int i = t; i < 8 * 128; i += 256) {
        int r = i >> 7;
        sh[r][i & 127] = __half2float(h[(size_t)(row0 + r) * 128 + (i & 127)]);
    }
    __syncthreads();
    int warp = t >> 5, lane = t & 31;
    int row = row0 + warp;
    float acc = 0.f;
#pragma unroll
    for (int k = 0; k < 128; k++) acc += sh[warp][k] * sw[k * 32 + lane];
    g_hlr[(size_t)row * 32 + lane] = acc;
}

// ---------------- conv2 aggregation + log_softmax ---------------------------
__global__ void conv2_agg(const float* __restrict__ att2, const float* __restrict__ b2,
                          float* __restrict__ out) {
    int tid = blockIdx.x * blockDim.x + threadIdx.x;
    int d = tid >> 4;
    int l = tid & 15;
    unsigned hm = 0xFFFFu << (((threadIdx.x & 31) >> 4) * 16);

    float xr = g_hlr[(size_t)d * 32 + 16 + l];
    float a  = att2[l];
    const int beg = g_rowptr[d], end = g_rowptr[d + 1];
    const int last = end - 1;

    float m = -INFINITY, s = 0.f, acc = 0.f;

    int i4[4];
    float r[4];
#pragma unroll
    for (int k = 0; k < 4; k++) {
        int j0 = min(beg + k, last);
        int j4 = min(beg + 4 + k, last);
        int src = g_csr[j0];
        i4[k] = g_csr[j4];
        r[k] = g_hlr[(size_t)src * 32 + l];
    }

    for (int j = beg; j < end; j++) {
        int inew = g_csr[min(j + 8, last)];
        float rnew = g_hlr[(size_t)i4[0] * 32 + l];

        float xl = r[0];
        float p = lrelu(xl + xr) * a;
        p += __shfl_xor_sync(hm, p, 1);
        p += __shfl_xor_sync(hm, p, 2);
        p += __shfl_xor_sync(hm, p, 4);
        p += __shfl_xor_sync(hm, p, 8);
        float mn = fmaxf(m, p);
        float f  = __expf(m - mn);
        float w  = __expf(p - mn);
        s   = s * f + w;
        acc = acc * f + xl * w;
        m = mn;

        r[0] = r[1]; r[1] = r[2]; r[2] = r[3]; r[3] = rnew;
        i4[0] = i4[1]; i4[1] = i4[2]; i4[2] = i4[3]; i4[3] = inew;
    }
    float v = acc / s + b2[l];
    float mm = v;
#pragma unroll
    for (int k = 8; k >= 1; k >>= 1) mm = fmaxf(mm, __shfl_xor_sync(hm, mm, k));
    float pe = expf(v - mm);
    float ss = pe;
#pragma unroll
    for (int k = 8; k >= 1; k >>= 1) ss += __shfl_xor_sync(hm, ss, k);
    out[(size_t)d * 16 + l] = v - mm - logf(ss);
}

// ---------------- side stream (created at static init) ---------------------
static cudaStream_t s_csr = 0;
static cudaEvent_t  ev_fork = 0, ev_join = 0;
namespace {
struct StreamInit {
    StreamInit() {
        cudaStreamCreateWithFlags(&s_csr, cudaStreamNonBlocking);
        cudaEventCreateWithFlags(&ev_fork, cudaEventDisableTiming);
        cudaEventCreateWithFlags(&ev_join, cudaEventDisableTiming);
    }
} s_init;
}

// ---------------- launch ----------------
extern "C" void kernel_launch(void* const* d_in, const int* in_sizes, int n_in,
                              void* d_out, int out_size) {
    const float* x    = (const float*)d_in[0];
    const void*  ei   = d_in[1];
    const float* Wl1  = (const float*)d_in[2];
    const float* Wr1  = (const float*)d_in[3];
    const float* att1 = (const float*)d_in[4];
    const float* b1   = (const float*)d_in[5];
    const float* Wk   = (const float*)d_in[6];
    const float* bk   = (const float*)d_in[7];
    const float* Wl2  = (const float*)d_in[8];
    const float* Wr2  = (const float*)d_in[9];
    const float* att2 = (const float*)d_in[10];
    const float* b2   = (const float*)d_in[11];
    float* out = (float*)d_out;

    cudaFuncSetAttribute(mma_gemm, cudaFuncAttributeMaxDynamicSharedMemorySize, SMEM_MMA_SZ);

    __half *xh, *xlh, *xrh, *h1h, *h2h;
    cudaGetSymbolAddress((void**)&xh,  g_x_h);
    cudaGetSymbolAddress((void**)&xlh, g_xl_h);
    cudaGetSymbolAddress((void**)&xrh, g_xr_h);
    cudaGetSymbolAddress((void**)&h1h, g_h1h);
    cudaGetSymbolAddress((void**)&h2h, g_h2h);

    // 1: weight fp16 images
    wconv<<<dim3(128, 5), 128>>>(Wl1, Wr1, Wk, Wk + 128 * 128, Wk + 2 * 128 * 128);
    // 2: deg=0 + dtype detect
    init_detect<<<NB, 256>>>(ei);
    // 3: x -> fp16 (numerically identical to in-GEMM convert)
    xconv<<<(NN * 128 / 8 + 255) / 256, 256>>>(x);

    // ---- fork: CSR build on side stream, conv1 GEMM on main stream ----
    cudaEventRecord(ev_fork, 0);
    cudaStreamWaitEvent(s_csr, ev_fork, 0);

    // 4: conv1 xl+xr transforms (PROFILED SLOT)
    mma_gemm<<<dim3(GX128, 2), 128, SMEM_MMA_SZ>>>(xh, 0, 1, xlh, xrh, nullptr, 0);
    // 5-9: CSR build (side stream; starts at fork event)
    degree_k <<<(EE + 255) / 256, 256, 0, s_csr>>>(ei);
    scan_part<<<NB, 256, 0, s_csr>>>();
    scan_mid <<<1, 256, 0, s_csr>>>();
    scan_add <<<NB, 256, 0, s_csr>>>();
    scatter_k<<<(EE + 255) / 256, 256, 0, s_csr>>>(ei);
    cudaEventRecord(ev_join, s_csr);

    // ---- join ----
    cudaStreamWaitEvent(0, ev_join, 0);

    // conv1 aggregation (+elu) -> h1 (fp16)
    conv1_agg<<<NN / 8, 256>>>(att1, b1);

    // knowledge layers (fp16 in/out, bias + elu fused)
    mma_gemm<<<dim3(GX128, 1), 128, SMEM_MMA_SZ>>>(h1h, 2, 2, h2h, h2h, bk,       1);
    mma_gemm<<<dim3(GX128, 1), 128, SMEM_MMA_SZ>>>(h2h, 3, 3, h1h, h1h, bk + 128, 1);
    mma_gemm<<<dim3(GX128, 1), 128, SMEM_MMA_SZ>>>(h1h, 4, 4, h2h, h2h, bk + 256, 1);

    // conv2 transforms (fp16 h) -> g_hlr (fp32)
    conv2_transform<<<NN / 8, 256>>>(h2h, Wl2, Wr2);

    // conv2 aggregation + log_softmax -> out
    conv2_agg<<<NN / 16, 256>>>(att2, b2, out);
}

// round 16
// speedup vs baseline: 1.1150x; 1.1150x over previous
#include <cuda_runtime.h>
#include <cuda_fp16.h>
#include <math.h>
#include <stdint.h>

#define NN 50000
#define EE 800000
#define ET 850000   // EE + NN self loops
#define NB 196      // ceil(NN/256)
#define GX128 391   // ceil(NN/128)
#define GPAD 136    // padded row: 136 fp16 = 272B (conflict-free ldmatrix)
#define SMEM_MMA_SZ (128 * GPAD * 2)   // 34816 B: single fp16 B image

// ---------------- scratch (static device allocations only) ----------------
__device__ __align__(16) __half g_xl_h[(size_t)NN * 128];
__device__ __align__(16) __half g_xr_h[(size_t)NN * 128];
__device__ __align__(16) __half g_h1h[(size_t)NN * 128];
__device__ __align__(16) __half g_h2h[(size_t)NN * 128];
__device__ float g_hlr[(size_t)NN * 32];
__device__ int   g_deg[NN];
__device__ int   g_rowptr[NN + 1];
__device__ int   g_cursor[NN];
__device__ int   g_csr[ET];
__device__ int   g_part[256];
__device__ int   g_is64;
__device__ __align__(16) __half g_wimg[5][128 * GPAD];

__device__ __forceinline__ float lrelu(float x) { return x > 0.f ? x : 0.2f * x; }
__device__ __forceinline__ float elu1 (float x) { return x > 0.f ? x : expm1f(x); }

__device__ __forceinline__ uint32_t smem_u32(const void* p) {
    uint32_t a;
    asm("{ .reg .u64 t; cvta.to.shared.u64 t, %1; cvt.u32.u64 %0, t; }"
        : "=r"(a) : "l"(p));
    return a;
}
__device__ __forceinline__ uint32_t pkh(float2 f) {
    __half2 h = __float22half2_rn(f);
    return *(uint32_t*)&h;
}

__device__ __forceinline__ void ldsm_x4t(uint32_t& r0, uint32_t& r1,
                                         uint32_t& r2, uint32_t& r3, uint32_t addr) {
    asm volatile("ldmatrix.sync.aligned.m8n8.x4.trans.shared.b16 {%0,%1,%2,%3}, [%4];"
        : "=r"(r0), "=r"(r1), "=r"(r2), "=r"(r3) : "r"(addr));
}
__device__ __forceinline__ void mma16816(float* d, const uint32_t* a,
                                         uint32_t b0, uint32_t b1) {
    asm volatile(
        "mma.sync.aligned.m16n8k16.row.col.f32.f16.f16.f32 "
        "{%0,%1,%2,%3}, {%4,%5,%6,%7}, {%8,%9}, {%0,%1,%2,%3};"
        : "+f"(d[0]), "+f"(d[1]), "+f"(d[2]), "+f"(d[3])
        : "r"(a[0]), "r"(a[1]), "r"(a[2]), "r"(a[3]), "r"(b0), "r"(b1));
}

// ---------------- weight convert kernel: W[k][n] -> fp16 image --------------
__global__ void wconv(const float* __restrict__ w0, const float* __restrict__ w1,
                      const float* __restrict__ w2, const float* __restrict__ w3,
                      const float* __restrict__ w4) {
    int b = blockIdx.y;
    const float* W = (b == 0) ? w0 : (b == 1) ? w1 : (b == 2) ? w2 : (b == 3) ? w3 : w4;
    int k = blockIdx.x, n = threadIdx.x;
    g_wimg[b][k * GPAD + n] = __float2half_rn(W[(size_t)k * 128 + n]);
}

// ---------------- tensor-core GEMM: C[NN,128] = A[NN,128] @ W --------------
// fp16 single-pass, fp32 accum. AHALF: A dtype (0=f32,1=f16). OHALF: C dtype.
// 128(M)x128(N) per 256-thread CTA, two sequential 64-col halves.
template <int AHALF, int OHALF>
__global__ void __launch_bounds__(256) mma_gemm(
    const void* __restrict__ Av, int i0, int i1,
    void* __restrict__ C0v, void* __restrict__ C1v,
    const float* __restrict__ bias, int act) {
    extern __shared__ __align__(16) __half sB[];   // fp16 image [128*GPAD]
    const int t = threadIdx.x, lane = t & 31, wid = t >> 5;
    const int mat = blockIdx.y;
    const int img = mat ? i1 : i0;
    void* Cv = mat ? C1v : C0v;
    const int m0 = blockIdx.x * 128 + wid * 16;

    // stage B image: 34816 B = 2176 uint4
    {
        const uint4* src = (const uint4*)&g_wimg[img][0];
        uint4* dst = (uint4*)sB;
        for (int i = t; i < 2176; i += 256) dst[i] = src[i];
    }
    __syncthreads();

    const int g  = lane >> 2;
    const int cp = (lane & 3) * 2;
    const bool v0 = (m0 + g) < NN;
    const bool v8 = (m0 + g + 8) < NN;

    const int bi   = lane >> 3;
    const int brow = (lane & 7) + (bi & 1) * 8;
    const int bcol = (bi >> 1) * 8;
    const uint32_t sbH = smem_u32(sB);

    const int r0w = m0 + g, r8w = m0 + g + 8;

#pragma unroll
    for (int nh = 0; nh < 2; nh++) {
        const uint32_t hoff = (uint32_t)nh * 128;
        float acc[8][4];
#pragma unroll
        for (int i = 0; i < 8; i++)
#pragma unroll
            for (int j = 0; j < 4; j++) acc[i][j] = 0.f;

        for (int ks = 0; ks < 8; ks++) {
            const int k0 = ks * 16;
            uint32_t ah[4];
            if (AHALF) {
                const __half* Ah = (const __half*)Av;
                ah[0] = v0 ? *(const uint32_t*)&Ah[(size_t)r0w * 128 + k0 + cp]     : 0u;
                ah[1] = v8 ? *(const uint32_t*)&Ah[(size_t)r8w * 128 + k0 + cp]     : 0u;
                ah[2] = v0 ? *(const uint32_t*)&Ah[(size_t)r0w * 128 + k0 + cp + 8] : 0u;
                ah[3] = v8 ? *(const uint32_t*)&Ah[(size_t)r8w * 128 + k0 + cp + 8] : 0u;
            } else {
                const float* Af = (const float*)Av;
                float2 f0 = v0 ? *(const float2*)&Af[(size_t)r0w * 128 + k0 + cp]     : make_float2(0.f, 0.f);
                float2 f1 = v8 ? *(const float2*)&Af[(size_t)r8w * 128 + k0 + cp]     : make_float2(0.f, 0.f);
                float2 f2 = v0 ? *(const float2*)&Af[(size_t)r0w * 128 + k0 + cp + 8] : make_float2(0.f, 0.f);
                float2 f3 = v8 ? *(const float2*)&Af[(size_t)r8w * 128 + k0 + cp + 8] : make_float2(0.f, 0.f);
                ah[0] = pkh(f0); ah[1] = pkh(f1); ah[2] = pkh(f2); ah[3] = pkh(f3);
            }

            const uint32_t rowoff = (uint32_t)((k0 + brow) * GPAD + bcol) * 2 + hoff;
#pragma unroll
            for (int ng = 0; ng < 4; ng++) {
                uint32_t b0, b1, b2, b3;
                ldsm_x4t(b0, b1, b2, b3, sbH + rowoff + ng * 32);
                mma16816(acc[2 * ng],     ah, b0, b1);
                mma16816(acc[2 * ng + 1], ah, b2, b3);
            }
        }

        // epilogue for this 64-col half
#pragma unroll
        for (int nt = 0; nt < 8; nt++) {
            int gc = nh * 64 + nt * 8 + cp;
            float v00 = acc[nt][0], v01 = acc[nt][1];
            float v10 = acc[nt][2], v11 = acc[nt][3];
            if (bias) {
                float b0v = bias[gc], b1v = bias[gc + 1];
                v00 += b0v; v01 += b1v; v10 += b0v; v11 += b1v;
            }
            if (act == 1) { v00 = elu1(v00); v01 = elu1(v01); v10 = elu1(v10); v11 = elu1(v11); }
            if (OHALF) {
                __half* Ch = (__half*)Cv;
                if (v0) *(uint32_t*)&Ch[(size_t)r0w * 128 + gc] = pkh(make_float2(v00, v01));
                if (v8) *(uint32_t*)&Ch[(size_t)r8w * 128 + gc] = pkh(make_float2(v10, v11));
            } else {
                float* Cf = (float*)Cv;
                if (v0) *(float2*)&Cf[(size_t)r0w * 128 + gc] = make_float2(v00, v01);
                if (v8) *(float2*)&Cf[(size_t)r8w * 128 + gc] = make_float2(v10, v11);
            }
        }
    }
}

// ---------------- init deg=0 + dtype detect (block 0) ----------------------
__global__ void init_detect(const void* ei) {
    int i = blockIdx.x * blockDim.x + threadIdx.x;
    if (i < NN) g_deg[i] = 0;
    if (blockIdx.x == 0) {
        __shared__ int cnt;
        if (threadIdx.x == 0) cnt = 0;
        __syncthreads();
        const unsigned* p = (const unsigned*)ei;
        int nz = 0;
        for (int k = threadIdx.x; k < 2048; k += 256)
            if (p[2 * k + 1] != 0u) nz++;
        if (nz) atomicAdd(&cnt, nz);
        __syncthreads();
        if (threadIdx.x == 0) g_is64 = (cnt < 8) ? 1 : 0;
    }
}

__device__ __forceinline__ int edge_val(const void* ei, int idx, int is64) {
    if (is64) return (int)((const long long*)ei)[idx];
    return ((const int*)ei)[idx];
}

__global__ void degree_k(const void* ei) {
    int i = blockIdx.x * blockDim.x + threadIdx.x;
    if (i >= EE) return;
    int is64 = g_is64;
    int dst = edge_val(ei, EE + i, is64);
    atomicAdd(&g_deg[dst], 1);
}

// ---------------- parallel scan over (deg[i]+1) ----------------------------
__global__ void scan_part() {
    int t = threadIdx.x, lane = t & 31, w = t >> 5;
    int i = blockIdx.x * 256 + t;
    int v = (i < NN) ? g_deg[i] + 1 : 0;
#pragma unroll
    for (int off = 16; off >= 1; off >>= 1) v += __shfl_xor_sync(0xffffffffu, v, off);
    __shared__ int ws[8];
    if (lane == 0) ws[w] = v;
    __syncthreads();
    if (t == 0) {
        int s = 0;
#pragma unroll
        for (int k = 0; k < 8; k++) s += ws[k];
        g_part[blockIdx.x] = s;
    }
}

__global__ void scan_mid() {
    int t = threadIdx.x, lane = t & 31, w = t >> 5;
    int d = (t < NB) ? g_part[t] : 0;
    int v = d;
#pragma unroll
    for (int off = 1; off < 32; off <<= 1) {
        int u = __shfl_up_sync(0xffffffffu, v, off);
        if (lane >= off) v += u;
    }
    __shared__ int ws[8];
    if (lane == 31) ws[w] = v;
    __syncthreads();
    if (w == 0 && lane < 8) {
        int s = ws[lane];
#pragma unroll
        for (int off = 1; off < 8; off <<= 1) {
            int u = __shfl_up_sync(0xffu, s, off);
            if (lane >= off) s += u;
        }
        ws[lane] = s;
    }
    __syncthreads();
    int incl = v + (w > 0 ? ws[w - 1] : 0);
    if (t < NB) g_part[t] = incl - d;
    if (t == 255) g_rowptr[NN] = incl;
}

__global__ void scan_add() {
    int t = threadIdx.x, lane = t & 31, w = t >> 5;
    int i = blockIdx.x * 256 + t;
    int d = (i < NN) ? g_deg[i] + 1 : 0;
    int v = d;
#pragma unroll
    for (int off = 1; off < 32; off <<= 1) {
        int u = __shfl_up_sync(0xffffffffu, v, off);
        if (lane >= off) v += u;
    }
    __shared__ int ws[8];
    if (lane == 31) ws[w] = v;
    __syncthreads();
    if (w == 0 && lane < 8) {
        int s = ws[lane];
#pragma unroll
        for (int off = 1; off < 8; off <<= 1) {
            int u = __shfl_up_sync(0xffu, s, off);
            if (lane >= off) s += u;
        }
        ws[lane] = s;
    }
    __syncthreads();
    int excl = g_part[blockIdx.x] + v - d + (w > 0 ? ws[w - 1] : 0);
    if (i < NN) {
        g_rowptr[i] = excl;
        g_csr[excl] = i;
        g_cursor[i] = excl + 1;
    }
}

__global__ void scatter_k(const void* ei) {
    int i = blockIdx.x * blockDim.x + threadIdx.x;
    if (i >= EE) return;
    int is64 = g_is64;
    int s = edge_val(ei, i, is64);
    int d = edge_val(ei, EE + i, is64);
    int pos = atomicAdd(&g_cursor[d], 1);
    g_csr[pos] = s;
}

// ---------------- conv1 aggregation: warp per node, 8-head online softmax --
__global__ void conv1_agg(const float* __restrict__ att1, const float* __restrict__ b1) {
    int gw   = (blockIdx.x * blockDim.x + threadIdx.x) >> 5;
    int lane = threadIdx.x & 31;
    int d = gw;
    const int c4 = lane * 4;

    uint2 xru = *(const uint2*)&g_xr_h[(size_t)d * 128 + c4];
    float2 xr01 = __half22float2(*(__half2*)&xru.x);
    float2 xr23 = __half22float2(*(__half2*)&xru.y);
    const float4 av = *(const float4*)&att1[c4];
    const float4 bb = *(const float4*)&b1[c4];
    const int beg = g_rowptr[d], end = g_rowptr[d + 1];
    const int last = end - 1;

    float m = -INFINITY, s = 0.f;
    float ax = 0.f, ay = 0.f, az = 0.f, aw = 0.f;

    int i4[4];
    uint2 r[4];
#pragma unroll
    for (int k = 0; k < 4; k++) {
        int j0 = min(beg + k, last);
        int j4 = min(beg + 4 + k, last);
        int src = g_csr[j0];
        i4[k] = g_csr[j4];
        r[k] = *(const uint2*)&g_xl_h[(size_t)src * 128 + c4];
    }

    for (int j = beg; j < end; j++) {
        int inew = g_csr[min(j + 8, last)];
        uint2 rnew = *(const uint2*)&g_xl_h[(size_t)i4[0] * 128 + c4];

        float2 x01 = __half22float2(*(__half2*)&r[0].x);
        float2 x23 = __half22float2(*(__half2*)&r[0].y);
        float ex = lrelu(x01.x + xr01.x);
        float ey = lrelu(x01.y + xr01.y);
        float ez = lrelu(x23.x + xr23.x);
        float ew = lrelu(x23.y + xr23.y);
        float p = ex * av.x + ey * av.y + ez * av.z + ew * av.w;
        p += __shfl_xor_sync(0xffffffffu, p, 1);
        p += __shfl_xor_sync(0xffffffffu, p, 2);
        float mn = fmaxf(m, p);
        float f  = __expf(m - mn);
        float wt = __expf(p - mn);
        s  = s * f + wt;
        ax = ax * f + x01.x * wt;
        ay = ay * f + x01.y * wt;
        az = az * f + x23.x * wt;
        aw = aw * f + x23.y * wt;
        m = mn;

        r[0] = r[1]; r[1] = r[2]; r[2] = r[3]; r[3] = rnew;
        i4[0] = i4[1]; i4[1] = i4[2]; i4[2] = i4[3]; i4[3] = inew;
    }
    float inv = 1.f / s;
    float o0 = elu1(ax * inv + bb.x);
    float o1 = elu1(ay * inv + bb.y);
    float o2 = elu1(az * inv + bb.z);
    float o3 = elu1(aw * inv + bb.w);
    uint2 ov;
    ov.x = pkh(make_float2(o0, o1));
    ov.y = pkh(make_float2(o2, o3));
    *(uint2*)&g_h1h[(size_t)d * 128 + c4] = ov;
}

// ---------------- conv2 transforms (fp16 h input) ---------------------------
__global__ void conv2_transform(const __half* __restrict__ h,
                                const float* __restrict__ Wl2,
                                const float* __restrict__ Wr2) {
    __shared__ float sw[128 * 32];
    __shared__ float sh[8][128];
    int t = threadIdx.x;
    for (int i = t; i < 128 * 16; i += 256) {
        int k = i >> 4, c = i & 15;
        sw[k * 32 + c]      = Wl2[i];
        sw[k * 32 + 16 + c] = Wr2[i];
    }
    int row0 = blockIdx.x * 8;
    for (int i = t; i < 8 * 128; i += 256) {
        int r = i >> 7;
        sh[r][i & 127] = __half2float(h[(size_t)(row0 + r) * 128 + (i & 127)]);
    }
    __syncthreads();
    int warp = t >> 5, lane = t & 31;
    int row = row0 + warp;
    float acc = 0.f;
#pragma unroll
    for (int k = 0; k < 128; k++) acc += sh[warp][k] * sw[k * 32 + lane];
    g_hlr[(size_t)row * 32 + lane] = acc;
}

// ---------------- conv2 aggregation + log_softmax ---------------------------
__global__ void conv2_agg(const float* __restrict__ att2, const float* __restrict__ b2,
                          float* __restrict__ out) {
    int tid = blockIdx.x * blockDim.x + threadIdx.x;
    int d = tid >> 4;
    int l = tid & 15;
    unsigned hm = 0xFFFFu << (((threadIdx.x & 31) >> 4) * 16);

    float xr = g_hlr[(size_t)d * 32 + 16 + l];
    float a  = att2[l];
    const int beg = g_rowptr[d], end = g_rowptr[d + 1];
    const int last = end - 1;

    float m = -INFINITY, s = 0.f, acc = 0.f;

    int i4[4];
    float r[4];
#pragma unroll
    for (int k = 0; k < 4; k++) {
        int j0 = min(beg + k, last);
        int j4 = min(beg + 4 + k, last);
        int src = g_csr[j0];
        i4[k] = g_csr[j4];
        r[k] = g_hlr[(size_t)src * 32 + l];
    }

    for (int j = beg; j < end; j++) {
        int inew = g_csr[min(j + 8, last)];
        float rnew = g_hlr[(size_t)i4[0] * 32 + l];

        float xl = r[0];
        float p = lrelu(xl + xr) * a;
        p += __shfl_xor_sync(hm, p, 1);
        p += __shfl_xor_sync(hm, p, 2);
        p += __shfl_xor_sync(hm, p, 4);
        p += __shfl_xor_sync(hm, p, 8);
        float mn = fmaxf(m, p);
        float f  = __expf(m - mn);
        float w  = __expf(p - mn);
        s   = s * f + w;
        acc = acc * f + xl * w;
        m = mn;

        r[0] = r[1]; r[1] = r[2]; r[2] = r[3]; r[3] = rnew;
        i4[0] = i4[1]; i4[1] = i4[2]; i4[2] = i4[3]; i4[3] = inew;
    }
    float v = acc / s + b2[l];
    float mm = v;
#pragma unroll
    for (int k = 8; k >= 1; k >>= 1) mm = fmaxf(mm, __shfl_xor_sync(hm, mm, k));
    float pe = expf(v - mm);
    float ss = pe;
#pragma unroll
    for (int k = 8; k >= 1; k >>= 1) ss += __shfl_xor_sync(hm, ss, k);
    out[(size_t)d * 16 + l] = v - mm - logf(ss);
}

// ---------------- side stream (created at static init) ---------------------
static cudaStream_t s_csr = 0;
static cudaEvent_t  ev_fork = 0, ev_join = 0;
namespace {
struct StreamInit {
    StreamInit() {
        cudaStreamCreateWithFlags(&s_csr, cudaStreamNonBlocking);
        cudaEventCreateWithFlags(&ev_fork, cudaEventDisableTiming);
        cudaEventCreateWithFlags(&ev_join, cudaEventDisableTiming);
    }
} s_init;
}

// ---------------- launch ----------------
extern "C" void kernel_launch(void* const* d_in, const int* in_sizes, int n_in,
                              void* d_out, int out_size) {
    const float* x    = (const float*)d_in[0];
    const void*  ei   = d_in[1];
    const float* Wl1  = (const float*)d_in[2];
    const float* Wr1  = (const float*)d_in[3];
    const float* att1 = (const float*)d_in[4];
    const float* b1   = (const float*)d_in[5];
    const float* Wk   = (const float*)d_in[6];
    const float* bk   = (const float*)d_in[7];
    const float* Wl2  = (const float*)d_in[8];
    const float* Wr2  = (const float*)d_in[9];
    const float* att2 = (const float*)d_in[10];
    const float* b2   = (const float*)d_in[11];
    float* out = (float*)d_out;

    cudaFuncSetAttribute(mma_gemm<0, 1>, cudaFuncAttributeMaxDynamicSharedMemorySize, SMEM_MMA_SZ);
    cudaFuncSetAttribute(mma_gemm<1, 1>, cudaFuncAttributeMaxDynamicSharedMemorySize, SMEM_MMA_SZ);

    __half *xlh, *xrh, *h1h, *h2h;
    cudaGetSymbolAddress((void**)&xlh, g_xl_h);
    cudaGetSymbolAddress((void**)&xrh, g_xr_h);
    cudaGetSymbolAddress((void**)&h1h, g_h1h);
    cudaGetSymbolAddress((void**)&h2h, g_h2h);

    // 1: deg=0 + dtype detect (only dependency of the side-stream chain)
    init_detect<<<NB, 256>>>(ei);

    // ---- fork: CSR build on side stream; wconv+GEMM on main stream ----
    cudaEventRecord(ev_fork, 0);
    cudaStreamWaitEvent(s_csr, ev_fork, 0);

    // 2: degrees (side stream)
    degree_k <<<(EE + 255) / 256, 256, 0, s_csr>>>(ei);
    // 3: weight fp16 images (main; overlaps degree pass)
    wconv<<<dim3(128, 5), 128>>>(Wl1, Wr1, Wk, Wk + 128 * 128, Wk + 2 * 128 * 128);
    // 4: conv1 xl+xr transforms (PROFILED SLOT — fp32 in, fp16 out)
    mma_gemm<0, 1><<<dim3(GX128, 2), 256, SMEM_MMA_SZ>>>(x, 0, 1, xlh, xrh, nullptr, 0);
    // 5-8: rest of CSR build (side stream)
    scan_part<<<NB, 256, 0, s_csr>>>();
    scan_mid <<<1, 256, 0, s_csr>>>();
    scan_add <<<NB, 256, 0, s_csr>>>();
    scatter_k<<<(EE + 255) / 256, 256, 0, s_csr>>>(ei);
    cudaEventRecord(ev_join, s_csr);

    // ---- join ----
    cudaStreamWaitEvent(0, ev_join, 0);

    // conv1 aggregation (+elu) -> h1 (fp16)
    conv1_agg<<<NN / 8, 256>>>(att1, b1);

    // knowledge layers (fp16 in/out, bias + elu fused)
    mma_gemm<1, 1><<<dim3(GX128, 1), 256, SMEM_MMA_SZ>>>(h1h, 2, 2, h2h, h2h, bk,       1);
    mma_gemm<1, 1><<<dim3(GX128, 1), 256, SMEM_MMA_SZ>>>(h2h, 3, 3, h1h, h1h, bk + 128, 1);
    mma_gemm<1, 1><<<dim3(GX128, 1), 256, SMEM_MMA_SZ>>>(h1h, 4, 4, h2h, h2h, bk + 256, 1);

    // conv2 transforms (fp16 h) -> g_hlr (fp32)
    conv2_transform<<<NN / 8, 256>>>(h2h, Wl2, Wr2);

    // conv2 aggregation + log_softmax -> out
    conv2_agg<<<NN / 16, 256>>>(att2, b2, out);
}